// round 16
// baseline (speedup 1.0000x reference)
#include <cuda_runtime.h>
#include <cuda_bf16.h>
#include <cuda_fp16.h>
#include <math.h>
#include <stdint.h>

#define Bb   2
#define Tt   2048
#define Cc   2048
#define NH   16
#define NKV  4
#define HD   128
#define QDIM (NH * HD)    // 2048
#define KDIM (NKV * HD)   // 512
#define NALL (QDIM + 2 * KDIM)   // 3072 fused projection width
#define MROWS (Bb * Tt)   // 4096

// ------------------------- device scratch (no allocs allowed) --------------
__device__ float2 g_rope[Tt * 64];
__device__ __half g_xh[(size_t)MROWS * Cc];
__device__ __half g_QKVh[(size_t)MROWS * NALL];
__device__ __half g_Oh[(size_t)MROWS * QDIM];
__device__ __half g_wAllT[(size_t)NALL * Cc];   // wq^T | wk^T (rope-interleaved rows) | wv^T
__device__ __half g_woT[(size_t)Cc * QDIM];

// ------------------------- PTX helpers (sm_80-era, base-target-safe) -------
__device__ __forceinline__ uint32_t smem_u32(const void* p) {
    uint32_t a;
    asm("{ .reg .u64 t; cvta.to.shared.u64 t, %1; cvt.u32.u64 %0, t; }" : "=r"(a) : "l"(p));
    return a;
}
__device__ __forceinline__ void cp16(uint32_t saddr, const void* g) {
    asm volatile("cp.async.cg.shared.global [%0], [%1], 16;" :: "r"(saddr), "l"(g));
}
#define CP_COMMIT() asm volatile("cp.async.commit_group;" ::: "memory")
template <int N> __device__ __forceinline__ void cp_wait() {
    asm volatile("cp.async.wait_group %0;" :: "n"(N) : "memory");
}
__device__ __forceinline__ void ldsm4(uint32_t* r, uint32_t addr) {
    asm volatile("ldmatrix.sync.aligned.m8n8.x4.shared.b16 {%0,%1,%2,%3}, [%4];"
                 : "=r"(r[0]), "=r"(r[1]), "=r"(r[2]), "=r"(r[3]) : "r"(addr));
}
__device__ __forceinline__ void ldsm4t(uint32_t* r, uint32_t addr) {
    asm volatile("ldmatrix.sync.aligned.m8n8.x4.trans.shared.b16 {%0,%1,%2,%3}, [%4];"
                 : "=r"(r[0]), "=r"(r[1]), "=r"(r[2]), "=r"(r[3]) : "r"(addr));
}
__device__ __forceinline__ void mma16816h(float* d, const uint32_t* a, const uint32_t* b) {
    asm("mma.sync.aligned.m16n8k16.row.col.f32.f16.f16.f32 "
        "{%0,%1,%2,%3}, {%4,%5,%6,%7}, {%8,%9}, {%0,%1,%2,%3};"
        : "+f"(d[0]), "+f"(d[1]), "+f"(d[2]), "+f"(d[3])
        : "r"(a[0]), "r"(a[1]), "r"(a[2]), "r"(a[3]), "r"(b[0]), "r"(b[1]));
}
__device__ __forceinline__ float ex2f(float x) {
    float r;
    asm("ex2.approx.f32 %0, %1;" : "=f"(r) : "f"(x));
    return r;
}
__device__ __forceinline__ uint32_t swz128(uint32_t o) { return o ^ ((o >> 3) & 0x70); }

// ------------------------- fused prep kernel -------------------------------
__global__ void prep_all(const float* __restrict__ x,
                         const float* __restrict__ wq, const float* __restrict__ wk,
                         const float* __restrict__ wv, const float* __restrict__ wo,
                         __half* __restrict__ xh,
                         __half* __restrict__ wallT, __half* __restrict__ woT)
{
    const int z = blockIdx.z;
    const int bx = blockIdx.x;
    const int tx = threadIdx.x, ty = threadIdx.y;  // 32x8
    const int tid = ty * 32 + tx;

    if (z < 4) {
        __shared__ float t[32][33];
        const float* src; __half* dst; int N, rowoff; bool interleave;
        if (z == 0)      { src = wq; N = QDIM; rowoff = 0;    dst = wallT; interleave = true;  }
        else if (z == 1) { src = wk; N = KDIM; rowoff = 2048; dst = wallT; interleave = true;  }
        else if (z == 2) { src = wv; N = KDIM; rowoff = 2560; dst = wallT; interleave = false; }
        else             { src = wo; N = QDIM; rowoff = 0;    dst = woT;   interleave = false; }
        const int n0 = (bx & 63) * 32;
        if (n0 >= N) return;
        const int k0 = (bx >> 6) * 32;
#pragma unroll
        for (int i = 0; i < 4; i++)
            t[ty + 8 * i][tx] = src[(size_t)(k0 + ty + 8 * i) * N + n0 + tx];
        __syncthreads();
#pragma unroll
        for (int i = 0; i < 4; i++) {
            int n = n0 + ty + 8 * i;
            int nr = n;
            if (interleave) {
                int f = n & 127;
                nr = (n & ~127) | ((f & 63) << 1) | (f >> 6);
            }
            dst[(size_t)(rowoff + nr) * Cc + k0 + tx] =
                __float2half_rn(t[tx][ty + 8 * i]);
        }
    } else if (z < 6) {
        const int n4 = MROWS * Cc / 4;
        int i = ((z - 4) * 4096 + bx) * 256 + tid;
        if (i >= n4) return;
        float4 v = ((const float4*)x)[i];
        __half2* d = (__half2*)xh;
        d[i * 2]     = __floats2half2_rn(v.x, v.y);
        d[i * 2 + 1] = __floats2half2_rn(v.z, v.w);
    } else {
        int i = bx * 256 + tid;
        if (i >= Tt * 64) return;
        const int t = i >> 6, f = i & 63;
        double inv = exp(-(double)f * 0.14391156831212787);  // ln(10000)/64
        double a = (double)t * inv;
        g_rope[i] = make_float2((float)sin(a), (float)cos(a));
    }
}

// ------------------------- single-term fp16 HMMA GEMM ------------------------
#define GSMEM (3 * 32768 + 128)
template <typename OutT, bool ROPE>
__global__ __launch_bounds__(256, 2) void gemm_f16(
    const __half* __restrict__ A, const __half* __restrict__ Bm,
    OutT* __restrict__ C, int Cstride, int Kdim)
{
    extern __shared__ char smraw[];
    const uint32_t sb = (smem_u32(smraw) + 127) & ~127u;
    const int tid = threadIdx.x;
    const int lane = tid & 31, wid = tid >> 5;
    const int wm = wid >> 1, wn = wid & 1;
    const int bm = blockIdx.y * 128, bn = blockIdx.x * 128;

    float acc[2][8][4];
#pragma unroll
    for (int i = 0; i < 2; i++)
#pragma unroll
        for (int t = 0; t < 8; t++)
#pragma unroll
            for (int e = 0; e < 4; e++) acc[i][t][e] = 0.0f;

    const int nch = Kdim >> 6;

    auto prefetch = [&](int ch) {
        const uint32_t st = sb + (ch % 3) * 32768;
        const int kc = ch << 6;
#pragma unroll
        for (int q = 0; q < 4; q++) {
            int idx = tid + q * 256;
            int r = idx >> 3, u = idx & 7;
            uint32_t so = swz128((uint32_t)(r * 128 + u * 16));
            cp16(st + so,         A  + (size_t)(bm + r) * Kdim + kc + u * 8);
            cp16(st + 16384 + so, Bm + (size_t)(bn + r) * Kdim + kc + u * 8);
        }
        CP_COMMIT();
    };

    prefetch(0);
    prefetch(1);
    const uint32_t arow = wm * 32 + (lane & 15);
    const uint32_t acb  = ((uint32_t)(lane >> 4)) << 4;
    const uint32_t brow = wn * 64 + (lane & 7) + (((uint32_t)(lane >> 4)) << 3);
    const uint32_t bcb  = (((uint32_t)(lane >> 3)) & 1u) << 4;

    for (int ch = 0; ch < nch; ch++) {
        if (ch + 2 < nch) { prefetch(ch + 2); cp_wait<2>(); }
        else if (ch + 1 < nch) cp_wait<1>();
        else cp_wait<0>();
        __syncthreads();
        const uint32_t st = sb + (ch % 3) * 32768;
#pragma unroll
        for (int s = 0; s < 4; s++) {
            const uint32_t kb = s * 32;
            uint32_t ah[2][4], bh[4][4];
#pragma unroll
            for (int i = 0; i < 2; i++)
                ldsm4(ah[i], st + swz128((arow + i * 16) * 128 + kb + acb));
#pragma unroll
            for (int j = 0; j < 4; j++)
                ldsm4(bh[j], st + 16384 + swz128((brow + j * 16) * 128 + kb + bcb));
#pragma unroll
            for (int i = 0; i < 2; i++)
#pragma unroll
                for (int t = 0; t < 8; t++)
                    mma16816h(acc[i][t], ah[i], &bh[t >> 1][(t & 1) * 2]);
        }
        __syncthreads();
    }

#pragma unroll
    for (int i = 0; i < 2; i++) {
        const int r0 = bm + wm * 32 + i * 16 + (lane >> 2);
#pragma unroll
        for (int t = 0; t < 8; t++) {
            const int c = bn + wn * 64 + t * 8 + (lane & 3) * 2;
            if constexpr (ROPE) {
                if (c < 2560) {  // q/k region: rotate pair (x1, x2) in fp32
                    const int j = (c & 127) >> 1;
                    {
                        const float2 sc = g_rope[(r0 & (Tt - 1)) * 64 + j];
                        float x1 = acc[i][t][0], x2 = acc[i][t][1];
                        acc[i][t][0] = x1 * sc.y - x2 * sc.x;
                        acc[i][t][1] = x2 * sc.y + x1 * sc.x;
                    }
                    {
                        const float2 sc = g_rope[((r0 + 8) & (Tt - 1)) * 64 + j];
                        float x1 = acc[i][t][2], x2 = acc[i][t][3];
                        acc[i][t][2] = x1 * sc.y - x2 * sc.x;
                        acc[i][t][3] = x2 * sc.y + x1 * sc.x;
                    }
                }
            }
            if constexpr (sizeof(OutT) == 2) {
                *(__half2*)(C + (size_t)r0 * Cstride + c) =
                    __floats2half2_rn(acc[i][t][0], acc[i][t][1]);
                *(__half2*)(C + (size_t)(r0 + 8) * Cstride + c) =
                    __floats2half2_rn(acc[i][t][2], acc[i][t][3]);
            } else {
                *(float2*)(C + (size_t)r0 * Cstride + c) =
                    make_float2(acc[i][t][0], acc[i][t][1]);
                *(float2*)(C + (size_t)(r0 + 8) * Cstride + c) =
                    make_float2(acc[i][t][2], acc[i][t][3]);
            }
        }
    }
}

// ------------------------- fp16 HMMA flash attention (r11 + 3-deep ring) ---
// Q 128 rows (warp owns 16 x 128), register-resident P, warp-local stats.
// K/V rings are 3-DEEP (slot = kt % 3) -> ONE __syncthreads per tile, with
// the tile-(kt+2) load issued immediately after it (its slot was last read
// in tile kt-1, which the barrier proves complete).
#define SQ  0                       // 32KB Q tile
#define SK  32768                   // 3 x 32KB K ring
#define SV  (32768 + 3 * 32768)     // 3 x 32KB V ring
#define ATT_SMEM (32768 + 3 * 32768 + 3 * 32768)   // 224KB

__global__ __launch_bounds__(256) void attn_hmma(
    const __half* __restrict__ QKV, __half* __restrict__ Oh)
{
    extern __shared__ char smraw[];
    const uint32_t sb = smem_u32(smraw);

    const int tid = threadIdx.x, lane = tid & 31, wid = tid >> 5;
    const int qt = (int)gridDim.x - 1 - (int)blockIdx.x;   // heavy tiles first
    const int g = blockIdx.y, b = blockIdx.z;
    const int kvh = g & (NKV - 1);
    const int q0 = qt * 128;
    const size_t qrow = (size_t)(b * Tt + q0);
    const int rq = wid * 16;           // warp's Q-row base within tile

    auto loadQ = [&]() {               // no commit (merged with loadKV(0))
        const __half* gq = QKV + qrow * NALL + g * HD;
#pragma unroll
        for (int q = 0; q < 8; q++) {
            int idx = tid + q * 256;
            int r = idx >> 4, u = idx & 15;
            uint32_t so = ((uint32_t)(u >> 3) << 14) + swz128((uint32_t)(r * 128 + (u & 7) * 16));
            cp16(sb + SQ + so, gq + (size_t)r * NALL + u * 8);
        }
    };
    auto loadKV = [&](int kt) {        // one commit group per tile
        const uint32_t buf = (uint32_t)(kt % 3) * 32768;
        const __half* gk = QKV + (size_t)(b * Tt + kt * 128) * NALL + 2048 + kvh * HD;
        const __half* gv = gk + 512;
#pragma unroll
        for (int q = 0; q < 8; q++) {
            int idx = tid + q * 256;
            int r = idx >> 4, u = idx & 15;
            uint32_t so = ((uint32_t)(u >> 3) << 14) + swz128((uint32_t)(r * 128 + (u & 7) * 16));
            cp16(sb + SK + buf + so, gk + (size_t)r * NALL + u * 8);
        }
#pragma unroll
        for (int q = 0; q < 8; q++) {
            int idx = tid + q * 256;
            int r = idx >> 4, u = idx & 15;
            uint32_t so = ((uint32_t)(u >> 3) << 14) + swz128((uint32_t)(r * 128 + (u & 7) * 16));
            cp16(sb + SV + buf + so, gv + (size_t)r * NALL + u * 8);
        }
        CP_COMMIT();
    };

    loadQ();
    loadKV(0);                          // group: {Q, K0, V0}
    if (qt >= 1) loadKV(1);             // group: {K1, V1}

    float o[16][4];
#pragma unroll
    for (int t = 0; t < 16; t++)
#pragma unroll
        for (int e = 0; e < 4; e++) o[t][e] = 0.0f;
    float m_r[2] = {-INFINITY, -INFINITY};
    float l_r[2] = {0.f, 0.f};

    const float pre = 0.08838834764831843f * 0.02f;   // (1/sqrt(128)) / 50
    const float K1  = 72.13475204444817f;             // 50 * log2(e)
    const float c3 = -0.33333333f, c5 = 0.13333333f, c7 = -0.05396825f;

    for (int kt = 0; kt <= qt; kt++) {
        if (kt < qt) cp_wait<1>(); else cp_wait<0>();
        __syncthreads();                  // tile kt data visible; tile kt-1 reads done
        if (kt + 2 <= qt) loadKV(kt + 2); // slot (kt+2)%3 == (kt-1)%3, freed above

        const uint32_t kbase = sb + SK + (uint32_t)(kt % 3) * 32768;
        const uint32_t vbase = sb + SV + (uint32_t)(kt % 3) * 32768;

        // ---- S = Q K^T : warp tile 16 x 128
        float s[16][4];
#pragma unroll
        for (int t = 0; t < 16; t++)
#pragma unroll
            for (int e = 0; e < 4; e++) s[t][e] = 0.0f;

#pragma unroll
        for (int ks = 0; ks < 8; ks++) {
            uint32_t ah[4];
            {
                uint32_t c = ks * 32 + ((uint32_t)(lane >> 4) << 4);
                uint32_t row = rq + (lane & 15);
                ldsm4(ah, sb + SQ + ((c >> 7) << 14) + swz128(row * 128 + (c & 127)));
            }
#pragma unroll
            for (int jt = 0; jt < 8; jt++) {
                uint32_t bh[4];
                uint32_t c = ks * 32 + (((uint32_t)(lane >> 3) & 1u) << 4);
                uint32_t j = jt * 16 + (lane & 7) + ((uint32_t)(lane >> 4) << 3);
                ldsm4(bh, kbase + ((c >> 7) << 14) + swz128(j * 128 + (c & 127)));
                mma16816h(s[jt * 2],     ah, bh);
                mma16816h(s[jt * 2 + 1], ah, bh + 2);
            }
        }

        // ---- softcap (folded poly, exp2 units) + causal mask + row max
        const bool diag = (kt == qt);
        float rmx[2] = {-INFINITY, -INFINITY};
#pragma unroll
        for (int t = 0; t < 16; t++)
#pragma unroll
            for (int e = 0; e < 4; e++) {
                float x = s[t][e] * pre;
                float x2 = x * x;
                float P = 1.0f + x2 * (c3 + x2 * (c5 + x2 * c7));
                float v = (x * K1) * P;
                if (diag) {
                    int r  = rq + (lane >> 2) + ((e >> 1) << 3);
                    int cc = t * 8 + ((lane & 3) << 1) + (e & 1);
                    if (cc > r) v = -1e30f;
                }
                s[t][e] = v;
                rmx[e >> 1] = fmaxf(rmx[e >> 1], v);
            }
#pragma unroll
        for (int h = 0; h < 2; h++) {
            rmx[h] = fmaxf(rmx[h], __shfl_xor_sync(0xffffffffu, rmx[h], 1));
            rmx[h] = fmaxf(rmx[h], __shfl_xor_sync(0xffffffffu, rmx[h], 2));
        }
        float corr[2];
#pragma unroll
        for (int h = 0; h < 2; h++) {
            float mo = m_r[h];
            float mn = fmaxf(mo, rmx[h]);
            corr[h] = ex2f(mo - mn);
            m_r[h] = mn;
        }

        // ---- p = ex2(v - m) packed straight into A-fragments; row sums
        uint32_t ph[8][4];
        float rsum[2] = {0.f, 0.f};
#pragma unroll
        for (int t = 0; t < 16; t++) {
            float p0 = ex2f(s[t][0] - m_r[0]);
            float p1 = ex2f(s[t][1] - m_r[0]);
            float p2 = ex2f(s[t][2] - m_r[1]);
            float p3 = ex2f(s[t][3] - m_r[1]);
            rsum[0] += p0 + p1;
            rsum[1] += p2 + p3;
            __half2 h01 = __floats2half2_rn(p0, p1);
            __half2 h23 = __floats2half2_rn(p2, p3);
            ph[t >> 1][((t & 1) << 1) + 0] = *(uint32_t*)&h01;
            ph[t >> 1][((t & 1) << 1) + 1] = *(uint32_t*)&h23;
        }
#pragma unroll
        for (int h = 0; h < 2; h++) {
            rsum[h] += __shfl_xor_sync(0xffffffffu, rsum[h], 1);
            rsum[h] += __shfl_xor_sync(0xffffffffu, rsum[h], 2);
            l_r[h] = l_r[h] * corr[h] + rsum[h];
        }
        // rescale O
#pragma unroll
        for (int t = 0; t < 16; t++) {
            o[t][0] *= corr[0];
            o[t][1] *= corr[0];
            o[t][2] *= corr[1];
            o[t][3] *= corr[1];
        }

        // ---- O += P V : warp tile 16 x 128, V via ldmatrix.trans
#pragma unroll
        for (int ks = 0; ks < 8; ks++) {
#pragma unroll
            for (int dt = 0; dt < 8; dt++) {
                uint32_t vb[4];
                uint32_t dbase = dt * 16 + ((uint32_t)(lane >> 4) << 3);
                uint32_t j = ks * 16 + (lane & 15);
                ldsm4t(vb, vbase + ((dbase >> 6) << 14) + swz128(j * 128 + (dbase & 63) * 2));
                mma16816h(o[dt * 2],     ph[ks], vb);
                mma16816h(o[dt * 2 + 1], ph[ks], vb + 2);
            }
        }
    }

    // ---- epilogue: normalize, write O fp16
#pragma unroll
    for (int h = 0; h < 2; h++) {
        int r = rq + (lane >> 2) + h * 8;
        float inv = 1.0f / l_r[h];
        size_t gro = (qrow + r) * QDIM + g * HD;
#pragma unroll
        for (int t = 0; t < 16; t++) {
            int cc = t * 8 + ((lane & 3) << 1);
            *(__half2*)(Oh + gro + cc) = __floats2half2_rn(
                o[t][h * 2 + 0] * inv, o[t][h * 2 + 1] * inv);
        }
    }
}

// ---------------------------------------------------------------------------
extern "C" void kernel_launch(void* const* d_in, const int* in_sizes, int n_in,
                              void* d_out, int out_size)
{
    const float* x  = (const float*)d_in[0];
    const float* wq = (const float*)d_in[2];
    const float* wk = (const float*)d_in[3];
    const float* wv = (const float*)d_in[4];
    const float* wo = (const float*)d_in[5];
    float* out = (float*)d_out;

    __half *xh, *qkvh, *oh, *wallT, *woT;
    cudaGetSymbolAddress((void**)&xh, g_xh);
    cudaGetSymbolAddress((void**)&qkvh, g_QKVh);
    cudaGetSymbolAddress((void**)&oh, g_Oh);
    cudaGetSymbolAddress((void**)&wallT, g_wAllT);
    cudaGetSymbolAddress((void**)&woT, g_woT);

    // ---- fused prep (transposes [rope-interleaved wq/wk] + x->fp16 + table)
    prep_all<<<dim3(4096, 1, 7), dim3(32, 8)>>>(x, wq, wk, wv, wo, xh, wallT, woT);

    // ---- fused QKV projection with in-epilogue RoPE -> fp16 QKV
    cudaFuncSetAttribute((const void*)gemm_f16<__half, true>,
                         cudaFuncAttributeMaxDynamicSharedMemorySize, GSMEM);
    cudaFuncSetAttribute((const void*)gemm_f16<float, false>,
                         cudaFuncAttributeMaxDynamicSharedMemorySize, GSMEM);
    gemm_f16<__half, true><<<dim3(NALL / 128, MROWS / 128), 256, GSMEM>>>(
        xh, wallT, qkvh, NALL, Cc);

    // ---- attention (fp16 HMMA, FA2 register P, 3-deep ring / 1 barrier)
    cudaFuncSetAttribute(attn_hmma, cudaFuncAttributeMaxDynamicSharedMemorySize, ATT_SMEM);
    attn_hmma<<<dim3(Tt / 128, NH, Bb), 256, ATT_SMEM>>>(qkvh, oh);

    // ---- output projection (fp16 HMMA) -> fp32 out
    gemm_f16<float, false><<<dim3(QDIM / 128, MROWS / 128), 256, GSMEM>>>(
        oh, woT, out, QDIM, Cc);
}

// round 17
// speedup vs baseline: 1.0592x; 1.0592x over previous
#include <cuda_runtime.h>
#include <cuda_bf16.h>
#include <cuda_fp16.h>
#include <math.h>
#include <stdint.h>

#define Bb   2
#define Tt   2048
#define Cc   2048
#define NH   16
#define NKV  4
#define HD   128
#define QDIM (NH * HD)    // 2048
#define KDIM (NKV * HD)   // 512
#define NALL (QDIM + 2 * KDIM)   // 3072 fused projection width
#define MROWS (Bb * Tt)   // 4096

// ------------------------- device scratch (no allocs allowed) --------------
__device__ float2 g_rope[Tt * 64];
__device__ __half g_xh[(size_t)MROWS * Cc];
__device__ __half g_QKVh[(size_t)MROWS * NALL];
__device__ __half g_Oh[(size_t)MROWS * QDIM];
__device__ __half g_wAllT[(size_t)NALL * Cc];   // wq^T | wk^T (rope-interleaved rows) | wv^T
__device__ __half g_woT[(size_t)Cc * QDIM];

// ------------------------- PTX helpers (sm_80-era, base-target-safe) -------
__device__ __forceinline__ uint32_t smem_u32(const void* p) {
    uint32_t a;
    asm("{ .reg .u64 t; cvta.to.shared.u64 t, %1; cvt.u32.u64 %0, t; }" : "=r"(a) : "l"(p));
    return a;
}
__device__ __forceinline__ void cp16(uint32_t saddr, const void* g) {
    asm volatile("cp.async.cg.shared.global [%0], [%1], 16;" :: "r"(saddr), "l"(g));
}
#define CP_COMMIT() asm volatile("cp.async.commit_group;" ::: "memory")
template <int N> __device__ __forceinline__ void cp_wait() {
    asm volatile("cp.async.wait_group %0;" :: "n"(N) : "memory");
}
__device__ __forceinline__ void ldsm4(uint32_t* r, uint32_t addr) {
    asm volatile("ldmatrix.sync.aligned.m8n8.x4.shared.b16 {%0,%1,%2,%3}, [%4];"
                 : "=r"(r[0]), "=r"(r[1]), "=r"(r[2]), "=r"(r[3]) : "r"(addr));
}
__device__ __forceinline__ void ldsm4t(uint32_t* r, uint32_t addr) {
    asm volatile("ldmatrix.sync.aligned.m8n8.x4.trans.shared.b16 {%0,%1,%2,%3}, [%4];"
                 : "=r"(r[0]), "=r"(r[1]), "=r"(r[2]), "=r"(r[3]) : "r"(addr));
}
__device__ __forceinline__ void mma16816h(float* d, const uint32_t* a, const uint32_t* b) {
    asm("mma.sync.aligned.m16n8k16.row.col.f32.f16.f16.f32 "
        "{%0,%1,%2,%3}, {%4,%5,%6,%7}, {%8,%9}, {%0,%1,%2,%3};"
        : "+f"(d[0]), "+f"(d[1]), "+f"(d[2]), "+f"(d[3])
        : "r"(a[0]), "r"(a[1]), "r"(a[2]), "r"(a[3]), "r"(b[0]), "r"(b[1]));
}
__device__ __forceinline__ float ex2f(float x) {
    float r;
    asm("ex2.approx.f32 %0, %1;" : "=f"(r) : "f"(x));
    return r;
}
__device__ __forceinline__ uint32_t swz128(uint32_t o) { return o ^ ((o >> 3) & 0x70); }

// ------------------------- fused prep kernel -------------------------------
// z 0: wq transpose (rope-interleaved rows)
// z 1: wk (rope-interleaved) + wv (plain) transposes, packed in one slice
// z 2: wo transpose
// z 3..4: x -> fp16.   z 5: rope sin/cos table.
__global__ void prep_all(const float* __restrict__ x,
                         const float* __restrict__ wq, const float* __restrict__ wk,
                         const float* __restrict__ wv, const float* __restrict__ wo,
                         __half* __restrict__ xh,
                         __half* __restrict__ wallT, __half* __restrict__ woT)
{
    const int z = blockIdx.z;
    const int bx = blockIdx.x;
    const int tx = threadIdx.x, ty = threadIdx.y;  // 32x8
    const int tid = ty * 32 + tx;

    if (z < 3) {
        __shared__ float t[32][33];
        const float* src; __half* dst; int N, rowoff, n0; bool interleave;
        if (z == 0) {
            src = wq; N = QDIM; rowoff = 0; dst = wallT; interleave = true;
            n0 = (bx & 63) * 32;
        } else if (z == 1) {
            int np = (bx & 63) * 32;            // 0..2016
            if (np < 512)        { src = wk; rowoff = 2048; interleave = true;  n0 = np; }
            else if (np < 1024)  { src = wv; rowoff = 2560; interleave = false; n0 = np - 512; }
            else return;
            N = KDIM; dst = wallT;
        } else {
            src = wo; N = QDIM; rowoff = 0; dst = woT; interleave = false;
            n0 = (bx & 63) * 32;
        }
        if (n0 >= N) return;
        const int k0 = (bx >> 6) * 32;
#pragma unroll
        for (int i = 0; i < 4; i++)
            t[ty + 8 * i][tx] = src[(size_t)(k0 + ty + 8 * i) * N + n0 + tx];
        __syncthreads();
#pragma unroll
        for (int i = 0; i < 4; i++) {
            int n = n0 + ty + 8 * i;
            int nr = n;
            if (interleave) {
                int f = n & 127;
                nr = (n & ~127) | ((f & 63) << 1) | (f >> 6);
            }
            dst[(size_t)(rowoff + nr) * Cc + k0 + tx] =
                __float2half_rn(t[tx][ty + 8 * i]);
        }
    } else if (z < 5) {
        const int n4 = MROWS * Cc / 4;
        int i = ((z - 3) * 4096 + bx) * 256 + tid;
        if (i >= n4) return;
        float4 v = ((const float4*)x)[i];
        __half2* d = (__half2*)xh;
        d[i * 2]     = __floats2half2_rn(v.x, v.y);
        d[i * 2 + 1] = __floats2half2_rn(v.z, v.w);
    } else {
        int i = bx * 256 + tid;
        if (i >= Tt * 64) return;
        const int t = i >> 6, f = i & 63;
        double inv = exp(-(double)f * 0.14391156831212787);  // ln(10000)/64
        double a = (double)t * inv;
        g_rope[i] = make_float2((float)sin(a), (float)cos(a));
    }
}

// ------------------------- single-term fp16 HMMA GEMM ------------------------
// When ROPE=true (QKV projection): epilogue applies the rotary rotation to
// the fp32 accumulators of q/k columns (< 2560) before f16 rounding. Thanks
// to the interleaved weight layout, each __half2 = one rope pair (f, f+64).
#define GSMEM (3 * 32768 + 128)
template <typename OutT, bool ROPE>
__global__ __launch_bounds__(256, 2) void gemm_f16(
    const __half* __restrict__ A, const __half* __restrict__ Bm,
    OutT* __restrict__ C, int Cstride, int Kdim)
{
    extern __shared__ char smraw[];
    const uint32_t sb = (smem_u32(smraw) + 127) & ~127u;
    const int tid = threadIdx.x;
    const int lane = tid & 31, wid = tid >> 5;
    const int wm = wid >> 1, wn = wid & 1;
    const int bm = blockIdx.y * 128, bn = blockIdx.x * 128;

    float acc[2][8][4];
#pragma unroll
    for (int i = 0; i < 2; i++)
#pragma unroll
        for (int t = 0; t < 8; t++)
#pragma unroll
            for (int e = 0; e < 4; e++) acc[i][t][e] = 0.0f;

    const int nch = Kdim >> 6;

    auto prefetch = [&](int ch) {
        const uint32_t st = sb + (ch % 3) * 32768;
        const int kc = ch << 6;
#pragma unroll
        for (int q = 0; q < 4; q++) {
            int idx = tid + q * 256;
            int r = idx >> 3, u = idx & 7;
            uint32_t so = swz128((uint32_t)(r * 128 + u * 16));
            cp16(st + so,         A  + (size_t)(bm + r) * Kdim + kc + u * 8);
            cp16(st + 16384 + so, Bm + (size_t)(bn + r) * Kdim + kc + u * 8);
        }
        CP_COMMIT();
    };

    prefetch(0);
    prefetch(1);
    const uint32_t arow = wm * 32 + (lane & 15);
    const uint32_t acb  = ((uint32_t)(lane >> 4)) << 4;
    const uint32_t brow = wn * 64 + (lane & 7) + (((uint32_t)(lane >> 4)) << 3);
    const uint32_t bcb  = (((uint32_t)(lane >> 3)) & 1u) << 4;

    for (int ch = 0; ch < nch; ch++) {
        if (ch + 2 < nch) { prefetch(ch + 2); cp_wait<2>(); }
        else if (ch + 1 < nch) cp_wait<1>();
        else cp_wait<0>();
        __syncthreads();
        const uint32_t st = sb + (ch % 3) * 32768;
#pragma unroll
        for (int s = 0; s < 4; s++) {
            const uint32_t kb = s * 32;
            uint32_t ah[2][4], bh[4][4];
#pragma unroll
            for (int i = 0; i < 2; i++)
                ldsm4(ah[i], st + swz128((arow + i * 16) * 128 + kb + acb));
#pragma unroll
            for (int j = 0; j < 4; j++)
                ldsm4(bh[j], st + 16384 + swz128((brow + j * 16) * 128 + kb + bcb));
#pragma unroll
            for (int i = 0; i < 2; i++)
#pragma unroll
                for (int t = 0; t < 8; t++)
                    mma16816h(acc[i][t], ah[i], &bh[t >> 1][(t & 1) * 2]);
        }
        __syncthreads();
    }

#pragma unroll
    for (int i = 0; i < 2; i++) {
        const int r0 = bm + wm * 32 + i * 16 + (lane >> 2);
#pragma unroll
        for (int t = 0; t < 8; t++) {
            const int c = bn + wn * 64 + t * 8 + (lane & 3) * 2;
            if constexpr (ROPE) {
                if (c < 2560) {  // q/k region: rotate pair (x1, x2) in fp32
                    const int j = (c & 127) >> 1;
                    {
                        const float2 sc = g_rope[(r0 & (Tt - 1)) * 64 + j];
                        float x1 = acc[i][t][0], x2 = acc[i][t][1];
                        acc[i][t][0] = x1 * sc.y - x2 * sc.x;
                        acc[i][t][1] = x2 * sc.y + x1 * sc.x;
                    }
                    {
                        const float2 sc = g_rope[((r0 + 8) & (Tt - 1)) * 64 + j];
                        float x1 = acc[i][t][2], x2 = acc[i][t][3];
                        acc[i][t][2] = x1 * sc.y - x2 * sc.x;
                        acc[i][t][3] = x2 * sc.y + x1 * sc.x;
                    }
                }
            }
            if constexpr (sizeof(OutT) == 2) {
                *(__half2*)(C + (size_t)r0 * Cstride + c) =
                    __floats2half2_rn(acc[i][t][0], acc[i][t][1]);
                *(__half2*)(C + (size_t)(r0 + 8) * Cstride + c) =
                    __floats2half2_rn(acc[i][t][2], acc[i][t][3]);
            } else {
                *(float2*)(C + (size_t)r0 * Cstride + c) =
                    make_float2(acc[i][t][0], acc[i][t][1]);
                *(float2*)(C + (size_t)(r0 + 8) * Cstride + c) =
                    make_float2(acc[i][t][2], acc[i][t][3]);
            }
        }
    }
}

// ------------------------- fp16 HMMA flash attention (r11/r15, validated) --
// Q 128 rows (warp owns 16 x 128), register-resident P, warp-local stats,
// K/V 128-row tiles double-buffered, loads issued at loop bottom.
#define SQ  0                     // 32KB Q tile
#define SK  32768                 // 2 x 32KB K (double buffer)
#define SV  (32768 + 65536)       // 2 x 32KB V
#define ATT_SMEM (32768 + 65536 + 65536)   // 160KB

__global__ __launch_bounds__(256) void attn_hmma(
    const __half* __restrict__ QKV, __half* __restrict__ Oh)
{
    extern __shared__ char smraw[];
    const uint32_t sb = smem_u32(smraw);

    const int tid = threadIdx.x, lane = tid & 31, wid = tid >> 5;
    const int qt = (int)gridDim.x - 1 - (int)blockIdx.x;   // heavy tiles first
    const int g = blockIdx.y, b = blockIdx.z;
    const int kvh = g & (NKV - 1);
    const int q0 = qt * 128;
    const size_t qrow = (size_t)(b * Tt + q0);
    const int rq = wid * 16;           // warp's Q-row base within tile

    auto loadQ = [&]() {
        const __half* gq = QKV + qrow * NALL + g * HD;
#pragma unroll
        for (int q = 0; q < 8; q++) {
            int idx = tid + q * 256;
            int r = idx >> 4, u = idx & 15;
            uint32_t so = ((uint32_t)(u >> 3) << 14) + swz128((uint32_t)(r * 128 + (u & 7) * 16));
            cp16(sb + SQ + so, gq + (size_t)r * NALL + u * 8);
        }
        CP_COMMIT();
    };
    auto loadKV = [&](int kt) {
        const uint32_t buf = (uint32_t)(kt & 1) * 32768;
        const __half* gk = QKV + (size_t)(b * Tt + kt * 128) * NALL + 2048 + kvh * HD;
        const __half* gv = gk + 512;
#pragma unroll
        for (int q = 0; q < 8; q++) {
            int idx = tid + q * 256;
            int r = idx >> 4, u = idx & 15;
            uint32_t so = ((uint32_t)(u >> 3) << 14) + swz128((uint32_t)(r * 128 + (u & 7) * 16));
            cp16(sb + SK + buf + so, gk + (size_t)r * NALL + u * 8);
        }
#pragma unroll
        for (int q = 0; q < 8; q++) {
            int idx = tid + q * 256;
            int r = idx >> 4, u = idx & 15;
            uint32_t so = ((uint32_t)(u >> 3) << 14) + swz128((uint32_t)(r * 128 + (u & 7) * 16));
            cp16(sb + SV + buf + so, gv + (size_t)r * NALL + u * 8);
        }
        CP_COMMIT();
    };

    loadQ();
    loadKV(0);
    if (qt >= 1) loadKV(1);

    float o[16][4];
#pragma unroll
    for (int t = 0; t < 16; t++)
#pragma unroll
        for (int e = 0; e < 4; e++) o[t][e] = 0.0f;
    float m_r[2] = {-INFINITY, -INFINITY};
    float l_r[2] = {0.f, 0.f};

    const float pre = 0.08838834764831843f * 0.02f;   // (1/sqrt(128)) / 50
    const float K1  = 72.13475204444817f;             // 50 * log2(e)
    const float c3 = -0.33333333f, c5 = 0.13333333f, c7 = -0.05396825f;

    for (int kt = 0; kt <= qt; kt++) {
        if (kt < qt) cp_wait<1>(); else cp_wait<0>();
        __syncthreads();                      // K(kt), V(kt) visible to all
        const uint32_t kbase = sb + SK + (uint32_t)(kt & 1) * 32768;
        const uint32_t vbase = sb + SV + (uint32_t)(kt & 1) * 32768;

        // ---- S = Q K^T : warp tile 16 x 128
        float s[16][4];
#pragma unroll
        for (int t = 0; t < 16; t++)
#pragma unroll
            for (int e = 0; e < 4; e++) s[t][e] = 0.0f;

#pragma unroll
        for (int ks = 0; ks < 8; ks++) {
            uint32_t ah[4];
            {
                uint32_t c = ks * 32 + ((uint32_t)(lane >> 4) << 4);
                uint32_t row = rq + (lane & 15);
                ldsm4(ah, sb + SQ + ((c >> 7) << 14) + swz128(row * 128 + (c & 127)));
            }
#pragma unroll
            for (int jt = 0; jt < 8; jt++) {
                uint32_t bh[4];
                uint32_t c = ks * 32 + (((uint32_t)(lane >> 3) & 1u) << 4);
                uint32_t j = jt * 16 + (lane & 7) + ((uint32_t)(lane >> 4) << 3);
                ldsm4(bh, kbase + ((c >> 7) << 14) + swz128(j * 128 + (c & 127)));
                mma16816h(s[jt * 2],     ah, bh);
                mma16816h(s[jt * 2 + 1], ah, bh + 2);
            }
        }

        // ---- softcap (folded poly, exp2 units) + causal mask + row max
        const bool diag = (kt == qt);
        float rmx[2] = {-INFINITY, -INFINITY};
#pragma unroll
        for (int t = 0; t < 16; t++)
#pragma unroll
            for (int e = 0; e < 4; e++) {
                float x = s[t][e] * pre;
                float x2 = x * x;
                float P = 1.0f + x2 * (c3 + x2 * (c5 + x2 * c7));
                float v = (x * K1) * P;
                if (diag) {
                    int r  = rq + (lane >> 2) + ((e >> 1) << 3);
                    int cc = t * 8 + ((lane & 3) << 1) + (e & 1);
                    if (cc > r) v = -1e30f;
                }
                s[t][e] = v;
                rmx[e >> 1] = fmaxf(rmx[e >> 1], v);
            }
#pragma unroll
        for (int h = 0; h < 2; h++) {
            rmx[h] = fmaxf(rmx[h], __shfl_xor_sync(0xffffffffu, rmx[h], 1));
            rmx[h] = fmaxf(rmx[h], __shfl_xor_sync(0xffffffffu, rmx[h], 2));
        }
        float corr[2];
#pragma unroll
        for (int h = 0; h < 2; h++) {
            float mo = m_r[h];
            float mn = fmaxf(mo, rmx[h]);
            corr[h] = ex2f(mo - mn);
            m_r[h] = mn;
        }

        // ---- p = ex2(v - m) packed straight into A-fragments; row sums
        uint32_t ph[8][4];
        float rsum[2] = {0.f, 0.f};
#pragma unroll
        for (int t = 0; t < 16; t++) {
            float p0 = ex2f(s[t][0] - m_r[0]);
            float p1 = ex2f(s[t][1] - m_r[0]);
            float p2 = ex2f(s[t][2] - m_r[1]);
            float p3 = ex2f(s[t][3] - m_r[1]);
            rsum[0] += p0 + p1;
            rsum[1] += p2 + p3;
            __half2 h01 = __floats2half2_rn(p0, p1);
            __half2 h23 = __floats2half2_rn(p2, p3);
            ph[t >> 1][((t & 1) << 1) + 0] = *(uint32_t*)&h01;
            ph[t >> 1][((t & 1) << 1) + 1] = *(uint32_t*)&h23;
        }
#pragma unroll
        for (int h = 0; h < 2; h++) {
            rsum[h] += __shfl_xor_sync(0xffffffffu, rsum[h], 1);
            rsum[h] += __shfl_xor_sync(0xffffffffu, rsum[h], 2);
            l_r[h] = l_r[h] * corr[h] + rsum[h];
        }
        // rescale O
#pragma unroll
        for (int t = 0; t < 16; t++) {
            o[t][0] *= corr[0];
            o[t][1] *= corr[0];
            o[t][2] *= corr[1];
            o[t][3] *= corr[1];
        }

        // ---- O += P V : warp tile 16 x 128, V via ldmatrix.trans
#pragma unroll
        for (int ks = 0; ks < 8; ks++) {
#pragma unroll
            for (int dt = 0; dt < 8; dt++) {
                uint32_t vb[4];
                uint32_t dbase = dt * 16 + ((uint32_t)(lane >> 4) << 3);
                uint32_t j = ks * 16 + (lane & 15);
                ldsm4t(vb, vbase + ((dbase >> 6) << 14) + swz128(j * 128 + (dbase & 63) * 2));
                mma16816h(o[dt * 2],     ph[ks], vb);
                mma16816h(o[dt * 2 + 1], ph[ks], vb + 2);
            }
        }

        __syncthreads();                      // all warps done with buf kt&1
        if (kt + 2 <= qt) loadKV(kt + 2);     // refill buf kt&1
    }

    // ---- epilogue: normalize, write O fp16
#pragma unroll
    for (int h = 0; h < 2; h++) {
        int r = rq + (lane >> 2) + h * 8;
        float inv = 1.0f / l_r[h];
        size_t gro = (qrow + r) * QDIM + g * HD;
#pragma unroll
        for (int t = 0; t < 16; t++) {
            int cc = t * 8 + ((lane & 3) << 1);
            *(__half2*)(Oh + gro + cc) = __floats2half2_rn(
                o[t][h * 2 + 0] * inv, o[t][h * 2 + 1] * inv);
        }
    }
}

// ---------------------------------------------------------------------------
extern "C" void kernel_launch(void* const* d_in, const int* in_sizes, int n_in,
                              void* d_out, int out_size)
{
    const float* x  = (const float*)d_in[0];
    const float* wq = (const float*)d_in[2];
    const float* wk = (const float*)d_in[3];
    const float* wv = (const float*)d_in[4];
    const float* wo = (const float*)d_in[5];
    float* out = (float*)d_out;

    __half *xh, *qkvh, *oh, *wallT, *woT;
    cudaGetSymbolAddress((void**)&xh, g_xh);
    cudaGetSymbolAddress((void**)&qkvh, g_QKVh);
    cudaGetSymbolAddress((void**)&oh, g_Oh);
    cudaGetSymbolAddress((void**)&wallT, g_wAllT);
    cudaGetSymbolAddress((void**)&woT, g_woT);

    // ---- fused prep (transposes [rope-interleaved wq/wk] + x->fp16 + table)
    prep_all<<<dim3(4096, 1, 6), dim3(32, 8)>>>(x, wq, wk, wv, wo, xh, wallT, woT);

    // ---- fused QKV projection with in-epilogue RoPE -> fp16 QKV
    cudaFuncSetAttribute((const void*)gemm_f16<__half, true>,
                         cudaFuncAttributeMaxDynamicSharedMemorySize, GSMEM);
    cudaFuncSetAttribute((const void*)gemm_f16<float, false>,
                         cudaFuncAttributeMaxDynamicSharedMemorySize, GSMEM);
    gemm_f16<__half, true><<<dim3(NALL / 128, MROWS / 128), 256, GSMEM>>>(
        xh, wallT, qkvh, NALL, Cc);

    // ---- attention (fp16 HMMA, FA2 register P — r11/r15 validated)
    cudaFuncSetAttribute(attn_hmma, cudaFuncAttributeMaxDynamicSharedMemorySize, ATT_SMEM);
    attn_hmma<<<dim3(Tt / 128, NH, Bb), 256, ATT_SMEM>>>(qkvh, oh);

    // ---- output projection (fp16 HMMA) -> fp32 out
    gemm_f16<float, false><<<dim3(QDIM / 128, MROWS / 128), 256, GSMEM>>>(
        oh, woT, out, QDIM, Cc);
}